// round 2
// baseline (speedup 1.0000x reference)
#include <cuda_runtime.h>
#include <math.h>

#define BB 2
#define LL 2048
#define DD 1024
#define HH 16
#define DH 64
#define TK 32
#define SCALE 0.125f   // 1/sqrt(64)

// ---------------- scratch (device globals; no allocs allowed) ----------------
__device__ float g_q   [(size_t)BB*LL*DD];          // q projection
__device__ float g_kv  [(size_t)BB*LL*2*DH];        // kv projection
__device__ float g_k   [(size_t)BB*LL*DH];          // normalized k
__device__ float g_v   [(size_t)BB*LL*DH];          // normalized v
__device__ float g_part[BB*16*128];                 // partial col sq-sums
__device__ float g_norm[BB*128];                    // col sq-sums (k|v)
__device__ float g_sims[(size_t)BB*HH*LL*LL];       // 512 MB sims
__device__ float g_rowmax[BB*HH*LL];
__device__ float g_rowsum[BB*HH*LL];
__device__ float g_topv[(size_t)BB*HH*LL*TK];
__device__ int   g_topi[(size_t)BB*HH*LL*TK];
__device__ float g_attn[(size_t)BB*LL*DD];          // local+retrieved

// ---------------- generic fp32 GEMM: C(MxN) = A(MxK) @ B(KxN) ----------------
// 128x64 tile, 256 threads, 8x4 micro. Requires M%128==0, N%64==0, K%16==0.
__global__ __launch_bounds__(256) void sgemm_kernel(
    const float* __restrict__ A, const float* __restrict__ Bm,
    float* __restrict__ C, int Mdim, int Ndim, int Kdim)
{
    __shared__ float As[128*17];   // [row][k]
    __shared__ float Bs[16*65];    // [k][col]
    int tid  = threadIdx.x;
    int brow = blockIdx.y * 128;
    int bcol = blockIdx.x * 64;
    int rowg = tid >> 4;           // 0..15
    int colg = tid & 15;           // 0..15
    float acc[8][4];
#pragma unroll
    for (int i = 0; i < 8; i++)
#pragma unroll
        for (int j = 0; j < 4; j++) acc[i][j] = 0.f;

    for (int kt = 0; kt < Kdim; kt += 16) {
        // load A tile: 128x16 = 512 float4
#pragma unroll
        for (int i = 0; i < 2; i++) {
            int f4 = tid + i*256;
            int r = f4 >> 2, c4 = f4 & 3;
            float4 v = *(const float4*)(A + (size_t)(brow + r)*Kdim + kt + c4*4);
            As[r*17 + c4*4+0] = v.x; As[r*17 + c4*4+1] = v.y;
            As[r*17 + c4*4+2] = v.z; As[r*17 + c4*4+3] = v.w;
        }
        // load B tile: 16x64 = 256 float4
        {
            int r = tid >> 4, c4 = tid & 15;
            float4 v = *(const float4*)(Bm + (size_t)(kt + r)*Ndim + bcol + c4*4);
            Bs[r*65 + c4*4+0] = v.x; Bs[r*65 + c4*4+1] = v.y;
            Bs[r*65 + c4*4+2] = v.z; Bs[r*65 + c4*4+3] = v.w;
        }
        __syncthreads();
#pragma unroll
        for (int kk = 0; kk < 16; kk++) {
            float av[8], bv[4];
#pragma unroll
            for (int i = 0; i < 8; i++) av[i] = As[(rowg + 16*i)*17 + kk];
#pragma unroll
            for (int j = 0; j < 4; j++) bv[j] = Bs[kk*65 + colg + 16*j];
#pragma unroll
            for (int i = 0; i < 8; i++)
#pragma unroll
                for (int j = 0; j < 4; j++) acc[i][j] += av[i]*bv[j];
        }
        __syncthreads();
    }
#pragma unroll
    for (int i = 0; i < 8; i++) {
        int r = brow + rowg + 16*i;
#pragma unroll
        for (int j = 0; j < 4; j++)
            C[(size_t)r*Ndim + bcol + colg + 16*j] = acc[i][j];
    }
}

// ---------------- sequence-axis L2 norm of k,v columns ----------------
__global__ void colsq_kernel() {   // grid 32 = b*16 chunks of 128 rows, 256 thr
    int b = blockIdx.x >> 4, chunk = blockIdx.x & 15;
    int j = threadIdx.x & 127, p = threadIdx.x >> 7;
    const float* base = g_kv + ((size_t)b*LL + chunk*128)*128;
    float ss = 0.f;
    for (int ll = p; ll < 128; ll += 2) {
        float v = base[ll*128 + j];
        ss += v*v;
    }
    __shared__ float sh[256];
    sh[threadIdx.x] = ss;
    __syncthreads();
    if (p == 0) g_part[(size_t)blockIdx.x*128 + j] = ss + sh[128 + j];
}

__global__ void normsum_kernel() {  // 1 block, 256 threads
    int tid = threadIdx.x;          // tid = b*128 + j
    int b = tid >> 7, j = tid & 127;
    float s = 0.f;
    for (int c = 0; c < 16; c++) s += g_part[(b*16 + c)*128 + j];
    g_norm[tid] = s;
}

__global__ void normalize_kernel() {  // grid BB*LL*128/256 = 2048
    int idx = blockIdx.x*256 + threadIdx.x;   // (b*LL+l)*128 + j
    int j  = idx & 127;
    int bl = idx >> 7;
    int b  = bl >> 11;
    float n = sqrtf(g_norm[b*128 + j]);
    n = fmaxf(n, 1e-12f);
    float v = g_kv[(size_t)idx] / n;
    if (j < 64) g_k[(size_t)bl*64 + j]        = v;
    else        g_v[(size_t)bl*64 + (j - 64)] = v;
}

// ---------------- sims = q @ k^T, 32 batches of 2048x2048x64 ----------------
// grid (mtile 16, ltile 16, z 32). 128x128 tile, full K=64, 8x8 micro.
__global__ __launch_bounds__(256) void sims_kernel() {
    extern __shared__ float sm[];
    float* Qs = sm;              // [128][65]
    float* Ks = sm + 128*65;     // [128][65]
    int z = blockIdx.z, b = z >> 4, h = z & 15;
    int lbase = blockIdx.y * 128, mbase = blockIdx.x * 128;
    const float* Aq = g_q + (size_t)b*LL*DD + h*DH;
    const float* Bk = g_k + (size_t)b*LL*DH;
    float* Cs = g_sims + (size_t)z*LL*LL;
    int tid = threadIdx.x;
#pragma unroll
    for (int i = 0; i < 8; i++) {
        int f4 = tid + i*256;    // 2048 f4 = 128 rows x 16
        int r = f4 >> 4, c4 = f4 & 15;
        float4 v = *(const float4*)(Aq + (size_t)(lbase + r)*DD + c4*4);
        Qs[r*65 + c4*4+0] = v.x; Qs[r*65 + c4*4+1] = v.y;
        Qs[r*65 + c4*4+2] = v.z; Qs[r*65 + c4*4+3] = v.w;
    }
#pragma unroll
    for (int i = 0; i < 8; i++) {
        int f4 = tid + i*256;
        int r = f4 >> 4, c4 = f4 & 15;
        float4 v = *(const float4*)(Bk + (size_t)(mbase + r)*DH + c4*4);
        Ks[r*65 + c4*4+0] = v.x; Ks[r*65 + c4*4+1] = v.y;
        Ks[r*65 + c4*4+2] = v.z; Ks[r*65 + c4*4+3] = v.w;
    }
    __syncthreads();
    int rowg = tid >> 4, colg = tid & 15;
    float acc[8][8];
#pragma unroll
    for (int i = 0; i < 8; i++)
#pragma unroll
        for (int j = 0; j < 8; j++) acc[i][j] = 0.f;
#pragma unroll 8
    for (int kk = 0; kk < 64; kk++) {
        float av[8], bv[8];
#pragma unroll
        for (int i = 0; i < 8; i++) av[i] = Qs[(rowg + 16*i)*65 + kk];
#pragma unroll
        for (int j = 0; j < 8; j++) bv[j] = Ks[(colg + 16*j)*65 + kk];
#pragma unroll
        for (int i = 0; i < 8; i++)
#pragma unroll
            for (int j = 0; j < 8; j++) acc[i][j] += av[i]*bv[j];
    }
#pragma unroll
    for (int i = 0; i < 8; i++) {
        size_t rowoff = (size_t)(lbase + rowg + 16*i)*LL + mbase;
#pragma unroll
        for (int j = 0; j < 8; j++)
            Cs[rowoff + colg + 16*j] = acc[i][j];
    }
}

// ---------------- per-row: max, sumexp, top-32 (iterated argmax) ------------
__global__ __launch_bounds__(256) void stats_topk_kernel() {  // grid 65536
    __shared__ float s[LL];
    __shared__ float redv[8];
    __shared__ int   redi[8];
    __shared__ float s_mx;
    size_t row = blockIdx.x;
    const float* S = g_sims + row * LL;
    int tid = threadIdx.x;
    int lane = tid & 31, wid = tid >> 5;
    for (int i = tid; i < LL/4; i += 256)
        ((float4*)s)[i] = ((const float4*)S)[i];
    __syncthreads();
    // row max
    float lm = -1e30f;
    for (int i = tid; i < LL; i += 256) lm = fmaxf(lm, s[i]);
#pragma unroll
    for (int o = 16; o; o >>= 1) lm = fmaxf(lm, __shfl_xor_sync(0xffffffffu, lm, o));
    if (lane == 0) redv[wid] = lm;
    __syncthreads();
    if (tid == 0) {
        float m = redv[0];
        for (int w = 1; w < 8; w++) m = fmaxf(m, redv[w]);
        s_mx = m;
        g_rowmax[row] = m;
    }
    __syncthreads();
    float mx = s_mx;
    // sum of exp
    float ls = 0.f;
    for (int i = tid; i < LL; i += 256) ls += __expf((s[i] - mx)*SCALE);
#pragma unroll
    for (int o = 16; o; o >>= 1) ls += __shfl_xor_sync(0xffffffffu, ls, o);
    if (lane == 0) redv[wid] = ls;
    __syncthreads();
    if (tid == 0) {
        float t = 0.f;
        for (int w = 0; w < 8; w++) t += redv[w];
        g_rowsum[row] = t;
    }
    __syncthreads();
    // top-32 by iterated argmax (destructive on smem copy)
    for (int it = 0; it < TK; it++) {
        float lv = -1e30f; int li = 0;
        for (int i = tid; i < LL; i += 256) {
            float v = s[i];
            if (v > lv) { lv = v; li = i; }
        }
#pragma unroll
        for (int o = 16; o; o >>= 1) {
            float ov = __shfl_xor_sync(0xffffffffu, lv, o);
            int   oi = __shfl_xor_sync(0xffffffffu, li, o);
            if (ov > lv) { lv = ov; li = oi; }
        }
        if (lane == 0) { redv[wid] = lv; redi[wid] = li; }
        __syncthreads();
        if (tid == 0) {
            float bv = redv[0]; int bi = redi[0];
            for (int w = 1; w < 8; w++)
                if (redv[w] > bv) { bv = redv[w]; bi = redi[w]; }
            g_topv[row*TK + it] = bv;
            g_topi[row*TK + it] = bi;
            s[bi] = -1e30f;
        }
        __syncthreads();
    }
}

// ---------------- local = softmax(sims*scale) @ v -------------------------
// grid (ltile 16, z 32). 128 rows x 64 cols, K-tiles of 64, 8x4 micro.
__global__ __launch_bounds__(256) void pv_kernel() {
    extern __shared__ float sm[];
    float* Ps  = sm;                // [128][65]
    float* Vs  = sm + 128*65;       // [64][65]
    float* smx = Vs + 64*65;        // [128]
    float* sis = smx + 128;         // [128]
    int z = blockIdx.y, b = z >> 4, h = z & 15;
    int lbase = blockIdx.x * 128;
    const float* S = g_sims + (size_t)z*LL*LL;
    int tid = threadIdx.x;
    if (tid < 128) {
        size_t row = (size_t)z*LL + lbase + tid;
        smx[tid] = g_rowmax[row];
        sis[tid] = 1.0f / g_rowsum[row];
    }
    __syncthreads();
    int rowg = tid >> 4, colg = tid & 15;
    float acc[8][4];
#pragma unroll
    for (int i = 0; i < 8; i++)
#pragma unroll
        for (int j = 0; j < 4; j++) acc[i][j] = 0.f;

    for (int mt = 0; mt < LL; mt += 64) {
#pragma unroll
        for (int i = 0; i < 8; i++) {
            int f4 = tid + i*256;      // 2048 f4 = 128 rows x 16
            int r = f4 >> 4, c4 = f4 & 15;
            float4 v = *(const float4*)(S + (size_t)(lbase + r)*LL + mt + c4*4);
            float m = smx[r], is = sis[r];
            Ps[r*65 + c4*4+0] = __expf((v.x - m)*SCALE)*is;
            Ps[r*65 + c4*4+1] = __expf((v.y - m)*SCALE)*is;
            Ps[r*65 + c4*4+2] = __expf((v.z - m)*SCALE)*is;
            Ps[r*65 + c4*4+3] = __expf((v.w - m)*SCALE)*is;
        }
#pragma unroll
        for (int i = 0; i < 4; i++) {
            int f4 = tid + i*256;      // 1024 f4 = 64 rows x 16
            int r = f4 >> 4, c4 = f4 & 15;
            float4 v = *(const float4*)(g_v + ((size_t)b*LL + mt + r)*DH + c4*4);
            Vs[r*65 + c4*4+0] = v.x; Vs[r*65 + c4*4+1] = v.y;
            Vs[r*65 + c4*4+2] = v.z; Vs[r*65 + c4*4+3] = v.w;
        }
        __syncthreads();
#pragma unroll 8
        for (int ml = 0; ml < 64; ml++) {
            float av[8], bv[4];
#pragma unroll
            for (int i = 0; i < 8; i++) av[i] = Ps[(rowg + 16*i)*65 + ml];
#pragma unroll
            for (int j = 0; j < 4; j++) bv[j] = Vs[ml*65 + colg + 16*j];
#pragma unroll
            for (int i = 0; i < 8; i++)
#pragma unroll
                for (int j = 0; j < 4; j++) acc[i][j] += av[i]*bv[j];
        }
        __syncthreads();
    }
#pragma unroll
    for (int i = 0; i < 8; i++) {
        size_t off = ((size_t)b*LL + lbase + rowg + 16*i)*DD + h*DH;
#pragma unroll
        for (int j = 0; j < 4; j++)
            g_attn[off + colg + 16*j] = acc[i][j];
    }
}

// ---------------- retrieved = softmax(topv*scale) @ k[topi] ----------------
// grid 8192 blocks x 256 thr; one warp per row (65536 rows total).
__global__ __launch_bounds__(256) void retrieved_kernel() {
    __shared__ float ps[8][32];
    __shared__ int   tis[8][32];
    int wid = threadIdx.x >> 5, lane = threadIdx.x & 31;
    size_t row = (size_t)blockIdx.x*8 + wid;
    int z = (int)(row >> 11), l = (int)(row & 2047);
    int b = z >> 4, h = z & 15;
    float tv = g_topv[row*TK + lane];
    int   ti = g_topi[row*TK + lane];
    float mx = __shfl_sync(0xffffffffu, tv, 0);   // topv sorted desc
    float p = __expf((tv - mx)*SCALE);
    float psum = p;
#pragma unroll
    for (int o = 16; o; o >>= 1) psum += __shfl_xor_sync(0xffffffffu, psum, o);
    ps[wid][lane] = p / psum;
    tis[wid][lane] = ti;
    __syncwarp();
    const float* kb = g_k + (size_t)b*LL*DH;
    float a0 = 0.f, a1 = 0.f;
#pragma unroll 8
    for (int t = 0; t < TK; t++) {
        float w = ps[wid][t];
        const float* kr = kb + (size_t)tis[wid][t]*DH;
        a0 += w * kr[lane];
        a1 += w * kr[lane + 32];
    }
    size_t off = ((size_t)b*LL + l)*DD + h*DH;
    g_attn[off + lane]      += a0;
    g_attn[off + lane + 32] += a1;
}

// ---------------- launch ----------------
extern "C" void kernel_launch(void* const* d_in, const int* in_sizes, int n_in,
                              void* d_out, int out_size)
{
    const float* q_in     = (const float*)d_in[0];
    const float* kv_in    = (const float*)d_in[1];
    const float* w_q      = (const float*)d_in[2];
    const float* w_kv     = (const float*)d_in[3];
    const float* w_concat = (const float*)d_in[4];
    float* out = (float*)d_out;

    float *p_q, *p_kv, *p_attn;
    cudaGetSymbolAddress((void**)&p_q,    g_q);
    cudaGetSymbolAddress((void**)&p_kv,   g_kv);
    cudaGetSymbolAddress((void**)&p_attn, g_attn);

    static const int SIMS_SMEM = 2*128*65*4;                       // 66560
    static const int PV_SMEM   = (128*65 + 64*65 + 256)*4;         // 50944
    cudaFuncSetAttribute(sims_kernel, cudaFuncAttributeMaxDynamicSharedMemorySize, SIMS_SMEM);
    cudaFuncSetAttribute(pv_kernel,   cudaFuncAttributeMaxDynamicSharedMemorySize, PV_SMEM);

    // 1. q = q_in @ w_q   (4096x1024x1024)
    sgemm_kernel<<<dim3(16, 32), 256>>>(q_in, w_q, p_q, BB*LL, DD, DD);
    // 2. kv = kv_in @ w_kv (4096x128x1024)
    sgemm_kernel<<<dim3(2, 32), 256>>>(kv_in, w_kv, p_kv, BB*LL, 2*DH, DD);
    // 3. l2 norm over sequence axis
    colsq_kernel<<<32, 256>>>();
    normsum_kernel<<<1, 256>>>();
    normalize_kernel<<<2048, 256>>>();
    // 4. sims
    sims_kernel<<<dim3(16, 16, 32), 256, SIMS_SMEM>>>();
    // 5. row stats + top-32
    stats_topk_kernel<<<BB*HH*LL, 256>>>();
    // 6. local attention (P@V) -> g_attn
    pv_kernel<<<dim3(16, 32), 256, PV_SMEM>>>();
    // 7. retrieved (+= into g_attn)
    retrieved_kernel<<<BB*HH*LL/8, 256>>>();
    // 8. out = attn @ w_concat
    sgemm_kernel<<<dim3(16, 32), 256>>>(p_attn, w_concat, out, BB*LL, DD, DD);
}

// round 3
// speedup vs baseline: 1.2728x; 1.2728x over previous
#include <cuda_runtime.h>
#include <math.h>

#define BB 2
#define LL 2048
#define DD 1024
#define HH 16
#define DH 64
#define TK 32
#define SCALE 0.125f   // 1/sqrt(64)

// ---------------- scratch (device globals; no allocs allowed) ----------------
__device__ float g_q   [(size_t)BB*LL*DD];
__device__ float g_kv  [(size_t)BB*LL*2*DH];
__device__ float g_k   [(size_t)BB*LL*DH];
__device__ float g_v   [(size_t)BB*LL*DH];
__device__ float g_part[BB*16*128];
__device__ float g_norm[BB*128];
__device__ float g_sims[(size_t)BB*HH*LL*LL];       // 512 MB
__device__ float g_rowmax[BB*HH*LL];
__device__ float g_rowsum[BB*HH*LL];
__device__ float g_topv[(size_t)BB*HH*LL*TK];
__device__ int   g_topi[(size_t)BB*HH*LL*TK];
__device__ float g_attn[(size_t)BB*LL*DD];

// ordered-uint key helpers (monotone float <-> uint map)
__device__ __forceinline__ unsigned f2key(float x) {
    unsigned u = __float_as_uint(x);
    return u ^ ((unsigned)((int)u >> 31) | 0x80000000u);
}
__device__ __forceinline__ float key2f(unsigned k) {
    unsigned u = (k & 0x80000000u) ? (k ^ 0x80000000u) : ~k;
    return __uint_as_float(u);
}

// ---------------- fp32 GEMM: C(MxN) = A(MxK) @ B(KxN) ----------------
// 128x128 tile, 256 threads, 8x8 micro (vectorized B reads / C writes).
// Requires M%128==0, N%128==0, K%32==0.
__global__ __launch_bounds__(256) void sgemm_kernel(
    const float* __restrict__ A, const float* __restrict__ Bm,
    float* __restrict__ C, int Mdim, int Ndim, int Kdim)
{
    __shared__ float As[128*33];   // [m][k] pad 33
    __shared__ float Bs[32*132];   // [k][n] pad 132
    int tid  = threadIdx.x;
    int brow = blockIdx.y * 128;
    int bcol = blockIdx.x * 128;
    int rowg = tid >> 4;             // 0..15
    int c0   = (tid & 15) * 4;       // 0..60
    float acc[8][8];
#pragma unroll
    for (int i = 0; i < 8; i++)
#pragma unroll
        for (int j = 0; j < 8; j++) acc[i][j] = 0.f;

    for (int kt = 0; kt < Kdim; kt += 32) {
        // A tile 128x32 : 1024 float4
#pragma unroll
        for (int i = 0; i < 4; i++) {
            int f4 = tid + i*256;
            int r = f4 >> 3, c4 = f4 & 7;
            float4 v = *(const float4*)(A + (size_t)(brow + r)*Kdim + kt + c4*4);
            As[r*33 + c4*4+0] = v.x; As[r*33 + c4*4+1] = v.y;
            As[r*33 + c4*4+2] = v.z; As[r*33 + c4*4+3] = v.w;
        }
        // B tile 32x128 : 1024 float4
#pragma unroll
        for (int i = 0; i < 4; i++) {
            int f4 = tid + i*256;
            int r = f4 >> 5, c4 = f4 & 31;
            *(float4*)&Bs[r*132 + c4*4] =
                *(const float4*)(Bm + (size_t)(kt + r)*Ndim + bcol + c4*4);
        }
        __syncthreads();
#pragma unroll 8
        for (int kk = 0; kk < 32; kk++) {
            float av[8];
#pragma unroll
            for (int i = 0; i < 8; i++) av[i] = As[(rowg + 16*i)*33 + kk];
            float4 b0 = *(float4*)&Bs[kk*132 + c0];
            float4 b1 = *(float4*)&Bs[kk*132 + 64 + c0];
#pragma unroll
            for (int i = 0; i < 8; i++) {
                acc[i][0] += av[i]*b0.x; acc[i][1] += av[i]*b0.y;
                acc[i][2] += av[i]*b0.z; acc[i][3] += av[i]*b0.w;
                acc[i][4] += av[i]*b1.x; acc[i][5] += av[i]*b1.y;
                acc[i][6] += av[i]*b1.z; acc[i][7] += av[i]*b1.w;
            }
        }
        __syncthreads();
    }
#pragma unroll
    for (int i = 0; i < 8; i++) {
        size_t r = (size_t)(brow + rowg + 16*i)*Ndim + bcol;
        *(float4*)(C + r + c0)      = make_float4(acc[i][0],acc[i][1],acc[i][2],acc[i][3]);
        *(float4*)(C + r + 64 + c0) = make_float4(acc[i][4],acc[i][5],acc[i][6],acc[i][7]);
    }
}

// ---------------- sequence-axis L2 norm of k,v columns ----------------
__global__ void colsq_kernel() {
    int b = blockIdx.x >> 4, chunk = blockIdx.x & 15;
    int j = threadIdx.x & 127, p = threadIdx.x >> 7;
    const float* base = g_kv + ((size_t)b*LL + chunk*128)*128;
    float ss = 0.f;
    for (int ll = p; ll < 128; ll += 2) {
        float v = base[ll*128 + j];
        ss += v*v;
    }
    __shared__ float sh[256];
    sh[threadIdx.x] = ss;
    __syncthreads();
    if (p == 0) g_part[(size_t)blockIdx.x*128 + j] = ss + sh[128 + j];
}

__global__ void normsum_kernel() {
    int tid = threadIdx.x;
    int b = tid >> 7, j = tid & 127;
    float s = 0.f;
    for (int c = 0; c < 16; c++) s += g_part[(b*16 + c)*128 + j];
    g_norm[tid] = s;
}

__global__ void normalize_kernel() {
    int idx = blockIdx.x*256 + threadIdx.x;
    int j  = idx & 127;
    int bl = idx >> 7;
    int b  = bl >> 11;
    float n = sqrtf(g_norm[b*128 + j]);
    n = fmaxf(n, 1e-12f);
    float v = g_kv[(size_t)idx] / n;
    if (j < 64) g_k[(size_t)bl*64 + j]        = v;
    else        g_v[(size_t)bl*64 + (j - 64)] = v;
}

// ---------------- sims = q @ k^T ----------------
// grid (mtile 16, ltile 16, z 32). 128x128 tile, K=64, 8x8 micro, vectorized.
__global__ __launch_bounds__(256) void sims_kernel() {
    extern __shared__ float sm[];
    float* Qs = sm;              // [128][65]  (l-rows x k)
    float* Kt = sm + 128*65;     // [64][132]  (k x m-rows, transposed)
    int z = blockIdx.z, b = z >> 4, h = z & 15;
    int lbase = blockIdx.y * 128, mbase = blockIdx.x * 128;
    const float* Aq = g_q + (size_t)b*LL*DD + h*DH;
    const float* Bk = g_k + (size_t)b*LL*DH;
    float* Cs = g_sims + (size_t)z*LL*LL;
    int tid = threadIdx.x;
#pragma unroll
    for (int i = 0; i < 8; i++) {            // Q tile 128x64
        int f4 = tid + i*256;
        int r = f4 >> 4, c4 = f4 & 15;
        float4 v = *(const float4*)(Aq + (size_t)(lbase + r)*DD + c4*4);
        Qs[r*65 + c4*4+0] = v.x; Qs[r*65 + c4*4+1] = v.y;
        Qs[r*65 + c4*4+2] = v.z; Qs[r*65 + c4*4+3] = v.w;
    }
#pragma unroll
    for (int i = 0; i < 8; i++) {            // K tile 128x64 -> transposed
        int f4 = tid + i*256;
        int lo = f4 & 31, hi = f4 >> 5;
        int r  = (lo & 7) + 8*(hi & 15);     // 0..127
        int c4 = (lo >> 3) + 4*(hi >> 4);    // 0..15
        float4 v = *(const float4*)(Bk + (size_t)(mbase + r)*DH + c4*4);
        Kt[(c4*4+0)*132 + r] = v.x; Kt[(c4*4+1)*132 + r] = v.y;
        Kt[(c4*4+2)*132 + r] = v.z; Kt[(c4*4+3)*132 + r] = v.w;
    }
    __syncthreads();
    int rowg = tid >> 4, c0 = (tid & 15)*4;
    float acc[8][8];
#pragma unroll
    for (int i = 0; i < 8; i++)
#pragma unroll
        for (int j = 0; j < 8; j++) acc[i][j] = 0.f;
#pragma unroll 8
    for (int kk = 0; kk < 64; kk++) {
        float av[8];
#pragma unroll
        for (int i = 0; i < 8; i++) av[i] = Qs[(rowg + 16*i)*65 + kk];
        float4 b0 = *(float4*)&Kt[kk*132 + c0];
        float4 b1 = *(float4*)&Kt[kk*132 + 64 + c0];
#pragma unroll
        for (int i = 0; i < 8; i++) {
            acc[i][0] += av[i]*b0.x; acc[i][1] += av[i]*b0.y;
            acc[i][2] += av[i]*b0.z; acc[i][3] += av[i]*b0.w;
            acc[i][4] += av[i]*b1.x; acc[i][5] += av[i]*b1.y;
            acc[i][6] += av[i]*b1.z; acc[i][7] += av[i]*b1.w;
        }
    }
#pragma unroll
    for (int i = 0; i < 8; i++) {
        size_t off = (size_t)(lbase + rowg + 16*i)*LL + mbase;
        *(float4*)(Cs + off + c0)      = make_float4(acc[i][0],acc[i][1],acc[i][2],acc[i][3]);
        *(float4*)(Cs + off + 64 + c0) = make_float4(acc[i][4],acc[i][5],acc[i][6],acc[i][7]);
    }
}

// ---------------- per-row: max, sumexp, top-32 (register-resident) ----------
__global__ __launch_bounds__(256) void stats_topk_kernel() {  // grid 65536
    __shared__ unsigned cand_key[256];
    __shared__ int      cand_idx[256];
    __shared__ float    redf[8];
    __shared__ unsigned redk[8];
    __shared__ float    s_mx;
    size_t row = blockIdx.x;
    const float* S = g_sims + row * LL;
    int tid = threadIdx.x, lane = tid & 31, wid = tid >> 5;

    float4 a = ((const float4*)S)[tid];
    float4 c = ((const float4*)S)[tid + 256];
    float v[8] = {a.x, a.y, a.z, a.w, c.x, c.y, c.z, c.w};
    unsigned key[8];
#pragma unroll
    for (int j = 0; j < 8; j++) key[j] = f2key(v[j]);

    // row max via redux on keys
    unsigned km = key[0];
#pragma unroll
    for (int j = 1; j < 8; j++) km = max(km, key[j]);
    km = __reduce_max_sync(0xffffffffu, km);
    if (lane == 0) redk[wid] = km;
    __syncthreads();
    if (tid == 0) {
        unsigned m = redk[0];
        for (int w = 1; w < 8; w++) m = max(m, redk[w]);
        float mx = key2f(m);
        s_mx = mx;
        g_rowmax[row] = mx;
    }
    __syncthreads();
    float mx = s_mx;

    // sum of exp
    float ls = 0.f;
#pragma unroll
    for (int j = 0; j < 8; j++) ls += __expf((v[j] - mx)*SCALE);
#pragma unroll
    for (int o = 16; o; o >>= 1) ls += __shfl_xor_sync(0xffffffffu, ls, o);
    if (lane == 0) redf[wid] = ls;
    __syncthreads();
    if (tid == 0) {
        float t = 0.f;
        for (int w = 0; w < 8; w++) t += redf[w];
        g_rowsum[row] = t;
    }

    // per-warp top-32 of its 256 elements (cached local max, redux argmax)
    unsigned lk = 0; int lj = 0;
#pragma unroll
    for (int j = 0; j < 8; j++) if (key[j] > lk) { lk = key[j]; lj = j; }
    for (int it = 0; it < TK; it++) {
        unsigned w = __reduce_max_sync(0xffffffffu, lk);
        unsigned ball = __ballot_sync(0xffffffffu, lk == w);
        int src = __ffs(ball) - 1;
        if (lane == src) {
            cand_key[wid*32 + it] = w;
            cand_idx[wid*32 + it] = (lj < 4) ? (4*tid + lj) : (1024 + 4*tid + lj - 4);
            key[lj] = 0u;
            lk = 0; lj = 0;
#pragma unroll
            for (int j = 0; j < 8; j++) if (key[j] > lk) { lk = key[j]; lj = j; }
        }
    }
    __syncthreads();

    // warp 0 merges 256 candidates -> global top-32 (sorted desc)
    if (wid == 0) {
        unsigned mkey[8]; int midx[8];
#pragma unroll
        for (int j = 0; j < 8; j++) {
            mkey[j] = cand_key[lane*8 + j];
            midx[j] = cand_idx[lane*8 + j];
        }
        unsigned mk = 0; int mj = 0;
#pragma unroll
        for (int j = 0; j < 8; j++) if (mkey[j] > mk) { mk = mkey[j]; mj = j; }
        for (int it = 0; it < TK; it++) {
            unsigned w = __reduce_max_sync(0xffffffffu, mk);
            unsigned ball = __ballot_sync(0xffffffffu, mk == w);
            int src = __ffs(ball) - 1;
            if (lane == src) {
                g_topv[row*TK + it] = key2f(w);
                g_topi[row*TK + it] = midx[mj];
                mkey[mj] = 0u;
                mk = 0; mj = 0;
#pragma unroll
                for (int j = 0; j < 8; j++) if (mkey[j] > mk) { mk = mkey[j]; mj = j; }
            }
        }
    }
}

// ---------------- local = softmax(sims*scale) @ v ----------------
// grid (ltile 8, z 32). 256 rows x 64 cols, K-tiles of 64, 16x4 micro.
__global__ __launch_bounds__(256) void pv_kernel() {
    extern __shared__ float sm[];
    float* Pt  = sm;                 // [64][260]  (m x l-rows, transposed, exp'd)
    float* Vs  = sm + 64*260;        // [64][68]
    float* smx = Vs + 64*68;         // [256]
    float* sis = smx + 256;          // [256]
    int z = blockIdx.y, b = z >> 4, h = z & 15;
    int lbase = blockIdx.x * 256;
    const float* S = g_sims + (size_t)z*LL*LL;
    int tid = threadIdx.x;
    {
        size_t row = (size_t)z*LL + lbase + tid;
        smx[tid] = g_rowmax[row];
        sis[tid] = 1.0f / g_rowsum[row];
    }
    __syncthreads();
    int rowg4 = (tid >> 4)*4;        // 0..60
    int c0    = (tid & 15)*4;        // 0..60
    float acc[16][4];
#pragma unroll
    for (int i = 0; i < 16; i++)
#pragma unroll
        for (int j = 0; j < 4; j++) acc[i][j] = 0.f;

    for (int mt = 0; mt < LL; mt += 64) {
        // S tile 256x64 -> exp -> transposed into Pt
#pragma unroll
        for (int i = 0; i < 16; i++) {
            int f4 = tid + i*256;                  // 0..4095
            int r  = (f4 & 7) + 8*((f4 >> 5) & 31);    // 0..255
            int c4 = ((f4 >> 3) & 3) + 4*(f4 >> 10);   // 0..15
            float4 v = *(const float4*)(S + (size_t)(lbase + r)*LL + mt + c4*4);
            float m = smx[r], is = sis[r];
            Pt[(c4*4+0)*260 + r] = __expf((v.x - m)*SCALE)*is;
            Pt[(c4*4+1)*260 + r] = __expf((v.y - m)*SCALE)*is;
            Pt[(c4*4+2)*260 + r] = __expf((v.z - m)*SCALE)*is;
            Pt[(c4*4+3)*260 + r] = __expf((v.w - m)*SCALE)*is;
        }
        // V tile 64x64
#pragma unroll
        for (int i = 0; i < 4; i++) {
            int f4 = tid + i*256;
            int r = f4 >> 4, c4 = f4 & 15;
            *(float4*)&Vs[r*68 + c4*4] =
                *(const float4*)(g_v + ((size_t)b*LL + mt + r)*DH + c4*4);
        }
        __syncthreads();
#pragma unroll 8
        for (int ml = 0; ml < 64; ml++) {
            float4 a0 = *(float4*)&Pt[ml*260 + rowg4];
            float4 a1 = *(float4*)&Pt[ml*260 + 64  + rowg4];
            float4 a2 = *(float4*)&Pt[ml*260 + 128 + rowg4];
            float4 a3 = *(float4*)&Pt[ml*260 + 192 + rowg4];
            float4 bv = *(float4*)&Vs[ml*68 + c0];
            float aq[16] = {a0.x,a0.y,a0.z,a0.w, a1.x,a1.y,a1.z,a1.w,
                            a2.x,a2.y,a2.z,a2.w, a3.x,a3.y,a3.z,a3.w};
#pragma unroll
            for (int i = 0; i < 16; i++) {
                acc[i][0] += aq[i]*bv.x; acc[i][1] += aq[i]*bv.y;
                acc[i][2] += aq[i]*bv.z; acc[i][3] += aq[i]*bv.w;
            }
        }
        __syncthreads();
    }
#pragma unroll
    for (int q = 0; q < 4; q++)
#pragma unroll
        for (int i = 0; i < 4; i++) {
            int r = lbase + q*64 + rowg4 + i;
            *(float4*)(g_attn + ((size_t)b*LL + r)*DD + h*DH + c0) =
                make_float4(acc[q*4+i][0],acc[q*4+i][1],acc[q*4+i][2],acc[q*4+i][3]);
        }
}

// ---------------- retrieved = softmax(topv*scale) @ k[topi] ----------------
__global__ __launch_bounds__(256) void retrieved_kernel() {
    __shared__ float ps[8][32];
    __shared__ int   tis[8][32];
    int wid = threadIdx.x >> 5, lane = threadIdx.x & 31;
    size_t row = (size_t)blockIdx.x*8 + wid;
    int z = (int)(row >> 11), l = (int)(row & 2047);
    int b = z >> 4, h = z & 15;
    float tv = g_topv[row*TK + lane];
    int   ti = g_topi[row*TK + lane];
    float mx = __shfl_sync(0xffffffffu, tv, 0);   // topv sorted desc
    float p = __expf((tv - mx)*SCALE);
    float psum = p;
#pragma unroll
    for (int o = 16; o; o >>= 1) psum += __shfl_xor_sync(0xffffffffu, psum, o);
    ps[wid][lane] = p / psum;
    tis[wid][lane] = ti;
    __syncwarp();
    const float* kb = g_k + (size_t)b*LL*DH;
    float a0 = 0.f, a1 = 0.f;
#pragma unroll 8
    for (int t = 0; t < TK; t++) {
        float w = ps[wid][t];
        const float* kr = kb + (size_t)tis[wid][t]*DH;
        a0 += w * kr[lane];
        a1 += w * kr[lane + 32];
    }
    size_t off = ((size_t)b*LL + l)*DD + h*DH;
    g_attn[off + lane]      += a0;
    g_attn[off + lane + 32] += a1;
}

// ---------------- launch ----------------
extern "C" void kernel_launch(void* const* d_in, const int* in_sizes, int n_in,
                              void* d_out, int out_size)
{
    const float* q_in     = (const float*)d_in[0];
    const float* kv_in    = (const float*)d_in[1];
    const float* w_q      = (const float*)d_in[2];
    const float* w_kv     = (const float*)d_in[3];
    const float* w_concat = (const float*)d_in[4];
    float* out = (float*)d_out;

    float *p_q, *p_kv, *p_attn;
    cudaGetSymbolAddress((void**)&p_q,    g_q);
    cudaGetSymbolAddress((void**)&p_kv,   g_kv);
    cudaGetSymbolAddress((void**)&p_attn, g_attn);

    static const int SIMS_SMEM = (128*65 + 64*132)*4;              // 67072
    static const int PV_SMEM   = (64*260 + 64*68 + 512)*4;         // 86016
    cudaFuncSetAttribute(sims_kernel, cudaFuncAttributeMaxDynamicSharedMemorySize, SIMS_SMEM);
    cudaFuncSetAttribute(pv_kernel,   cudaFuncAttributeMaxDynamicSharedMemorySize, PV_SMEM);

    // 1. q = q_in @ w_q   (4096x1024x1024)
    sgemm_kernel<<<dim3(8, 32), 256>>>(q_in, w_q, p_q, BB*LL, DD, DD);
    // 2. kv = kv_in @ w_kv (4096x128x1024)
    sgemm_kernel<<<dim3(1, 32), 256>>>(kv_in, w_kv, p_kv, BB*LL, 2*DH, DD);
    // 3. l2 norm over sequence axis
    colsq_kernel<<<32, 256>>>();
    normsum_kernel<<<1, 256>>>();
    normalize_kernel<<<2048, 256>>>();
    // 4. sims
    sims_kernel<<<dim3(16, 16, 32), 256, SIMS_SMEM>>>();
    // 5. row stats + top-32
    stats_topk_kernel<<<BB*HH*LL, 256>>>();
    // 6. local attention (P@V) -> g_attn
    pv_kernel<<<dim3(8, 32), 256, PV_SMEM>>>();
    // 7. retrieved (+= into g_attn)
    retrieved_kernel<<<BB*HH*LL/8, 256>>>();
    // 8. out = attn @ w_concat
    sgemm_kernel<<<dim3(8, 32), 256>>>(p_attn, w_concat, out, BB*LL, DD, DD);
}